// round 1
// baseline (speedup 1.0000x reference)
#include <cuda_runtime.h>
#include <math.h>

static constexpr int NN = 100000;     // nodes
static constexpr int NE = 1600000;    // edges
static constexpr int D  = 128;        // all feature dims

// ---------------- scratch (no allocations allowed) ----------------
__device__ float g_h[NN * D];
__device__ float g_nbuf[NN * D];
__device__ float g_tmp[NN * D];
__device__ int   g_counts[NN];
__device__ int   g_offsets[NN + 1];
__device__ int   g_cursor[NN];
__device__ float g_degw[NN];
__device__ int   g_csr_src[NE];
__device__ float g_csr_w[NE];
__device__ float g_colsum[D];
__device__ float g_colsumsq[D];
__device__ float g_scale[D];
__device__ float g_shift[D];

// ---------------- f32x2 packed math helpers (Blackwell FFMA2) ----------------
__device__ __forceinline__ unsigned long long pack2(float x, float y) {
    unsigned long long r;
    asm("mov.b64 %0, {%1, %2};" : "=l"(r) : "f"(x), "f"(y));
    return r;
}
__device__ __forceinline__ void ffma2(unsigned long long& d, unsigned long long a,
                                      unsigned long long b) {
    asm("fma.rn.f32x2 %0, %1, %2, %0;" : "+l"(d) : "l"(a), "l"(b));
}
__device__ __forceinline__ float lo32(unsigned long long v) {
    return __uint_as_float((unsigned)(v & 0xffffffffull));
}
__device__ __forceinline__ float hi32(unsigned long long v) {
    return __uint_as_float((unsigned)(v >> 32));
}

// ---------------- zero scratch counters ----------------
__global__ void zero_kernel() {
    int i = blockIdx.x * blockDim.x + threadIdx.x;
    if (i < NN) { g_counts[i] = 0; g_degw[i] = 0.f; }
    if (i < D)  { g_colsum[i] = 0.f; g_colsumsq[i] = 0.f; }
}

// ---------------- degree histogram ----------------
__global__ void hist_kernel(const int* __restrict__ col, const float* __restrict__ ew) {
    int i = blockIdx.x * blockDim.x + threadIdx.x;
    if (i < NE) {
        int c = col[i];
        atomicAdd(&g_counts[c], 1);
        atomicAdd(&g_degw[c], ew[i]);
    }
}

// ---------------- exclusive scan (single block, warp-shuffle) ----------------
__global__ void scan_kernel() {
    __shared__ int warpsums[32];
    __shared__ int s_carry;
    int tid = threadIdx.x, lane = tid & 31, wid = tid >> 5;
    if (tid == 0) s_carry = 0;
    __syncthreads();
    for (int base = 0; base < NN; base += 1024) {
        int i = base + tid;
        int v = (i < NN) ? g_counts[i] : 0;
        int x = v;
        #pragma unroll
        for (int off = 1; off < 32; off <<= 1) {
            int t = __shfl_up_sync(0xffffffffu, x, off);
            if (lane >= off) x += t;
        }
        if (lane == 31) warpsums[wid] = x;
        __syncthreads();
        if (wid == 0) {
            int ws = warpsums[lane];
            #pragma unroll
            for (int off = 1; off < 32; off <<= 1) {
                int t = __shfl_up_sync(0xffffffffu, ws, off);
                if (lane >= off) ws += t;
            }
            warpsums[lane] = ws;
        }
        __syncthreads();
        int warpoff = (wid == 0) ? 0 : warpsums[wid - 1];
        int excl = s_carry + warpoff + x - v;
        if (i < NN) { g_offsets[i] = excl; g_cursor[i] = excl; }
        int chunk_total = warpsums[31];
        __syncthreads();
        if (tid == 0) s_carry += chunk_total;
        __syncthreads();
    }
    if (tid == 0) g_offsets[NN] = s_carry;
}

// ---------------- CSR scatter ----------------
__global__ void scatter_kernel(const int* __restrict__ row, const int* __restrict__ col,
                               const float* __restrict__ ew) {
    int i = blockIdx.x * blockDim.x + threadIdx.x;
    if (i < NE) {
        int c = col[i];
        int p = atomicAdd(&g_cursor[c], 1);
        g_csr_src[p] = row[i];
        g_csr_w[p]   = ew[i];
    }
}

// ---------------- per-node weighted-mean aggregation (warp per node) ----------------
__global__ void aggregate_kernel() {
    int warp = (blockIdx.x * blockDim.x + threadIdx.x) >> 5;
    int lane = threadIdx.x & 31;
    if (warp >= NN) return;
    int start = g_offsets[warp], end = g_offsets[warp + 1];
    float4 acc = make_float4(0.f, 0.f, 0.f, 0.f);
    for (int e = start; e < end; e += 32) {
        int idx = e + lane;
        int s = 0; float w = 0.f;
        if (idx < end) { s = g_csr_src[idx]; w = g_csr_w[idx]; }
        int cnt = min(32, end - e);
        for (int j = 0; j < cnt; j++) {
            int   sj = __shfl_sync(0xffffffffu, s, j);
            float wj = __shfl_sync(0xffffffffu, w, j);
            float4 v = *(const float4*)(g_h + (long long)sj * D + lane * 4);
            acc.x += v.x * wj; acc.y += v.y * wj;
            acc.z += v.z * wj; acc.w += v.w * wj;
        }
    }
    float d = fmaxf(g_degw[warp], 1.0f);
    float inv = 1.0f / d;
    acc.x *= inv; acc.y *= inv; acc.z *= inv; acc.w *= inv;
    *(float4*)(g_nbuf + (long long)warp * D + lane * 4) = acc;
}

// ---------------- fused GEMM: out = A1@W1 (+ A2@W2) + bias, opt relu / col-stats ----
// Tile 128x128, 256 threads, 8x8 microtile with FFMA2 (col-paired accumulators).
template <int KTOT, bool RELU, bool STATS>
__global__ void __launch_bounds__(256, 1)
gemm128(const float* __restrict__ A1, const float* __restrict__ W1,
        const float* __restrict__ A2, const float* __restrict__ W2,
        const float* __restrict__ bias1, const float* __restrict__ bias2,
        float* __restrict__ out, int M) {
    extern __shared__ float smem[];
    float* Bs = smem;               // KTOT x 128
    float* As = smem + KTOT * D;    // 128 x 16

    const int tid = threadIdx.x;
    const int tx = tid & 15, ty = tid >> 4;
    const int row0 = blockIdx.x * 128;

    // stage weights (both matrices stacked on K)
    for (int i = tid * 4; i < KTOT * D; i += 256 * 4) {
        int k = i >> 7, n = i & 127;
        const float* W = (KTOT == 256 && k >= 128) ? (W2 + (k - 128) * D) : (W1 + k * D);
        *(float4*)(Bs + i) = *(const float4*)(W + n);
    }

    unsigned long long acc[8][4];
    #pragma unroll
    for (int r = 0; r < 8; r++)
        #pragma unroll
        for (int c = 0; c < 4; c++) acc[r][c] = 0ull;

    for (int kt = 0; kt < KTOT; kt += 16) {
        const float* Asrc = (KTOT == 256 && kt >= 128) ? A2 : A1;
        int kbase = (KTOT == 256 && kt >= 128) ? (kt - 128) : kt;
        __syncthreads();
        #pragma unroll
        for (int i = tid; i < 512; i += 256) {   // 128 rows x 16 k = 512 float4
            int r = i >> 2;
            int kc = (i & 3) * 4;
            int grow = row0 + r;
            float4 v = make_float4(0.f, 0.f, 0.f, 0.f);
            if (grow < M) v = *(const float4*)(Asrc + (long long)grow * D + kbase + kc);
            *(float4*)(As + r * 16 + kc) = v;
        }
        __syncthreads();
        #pragma unroll
        for (int kk = 0; kk < 16; kk++) {
            unsigned long long b[4];
            #pragma unroll
            for (int c = 0; c < 4; c++)
                b[c] = *(const unsigned long long*)(Bs + (kt + kk) * D + tx * 8 + c * 2);
            #pragma unroll
            for (int r = 0; r < 8; r++) {
                float a = As[(ty * 8 + r) * 16 + kk];
                unsigned long long a2 = pack2(a, a);
                #pragma unroll
                for (int c = 0; c < 4; c++) ffma2(acc[r][c], a2, b[c]);
            }
        }
    }
    __syncthreads();

    float bsum[8];
    #pragma unroll
    for (int c = 0; c < 8; c++) {
        int cc = tx * 8 + c;
        bsum[c] = bias1[cc] + (bias2 ? bias2[cc] : 0.f);
    }

    float csm[8], csq[8];
    #pragma unroll
    for (int c = 0; c < 8; c++) { csm[c] = 0.f; csq[c] = 0.f; }

    #pragma unroll
    for (int r = 0; r < 8; r++) {
        int grow = row0 + ty * 8 + r;
        if (grow < M) {
            float v[8];
            #pragma unroll
            for (int c2 = 0; c2 < 4; c2++) {
                v[2 * c2]     = lo32(acc[r][c2]);
                v[2 * c2 + 1] = hi32(acc[r][c2]);
            }
            #pragma unroll
            for (int c = 0; c < 8; c++) {
                v[c] += bsum[c];
                if (RELU) v[c] = fmaxf(v[c], 0.f);
                if (STATS) { csm[c] += v[c]; csq[c] += v[c] * v[c]; }
            }
            float* op = out + (long long)grow * D + tx * 8;
            *(float4*)(op)     = make_float4(v[0], v[1], v[2], v[3]);
            *(float4*)(op + 4) = make_float4(v[4], v[5], v[6], v[7]);
        }
    }

    if (STATS) {
        float* s_sum = As;        // reuse A tile smem
        float* s_sq  = As + D;
        if (tid < D) { s_sum[tid] = 0.f; s_sq[tid] = 0.f; }
        __syncthreads();
        #pragma unroll
        for (int c = 0; c < 8; c++) {
            atomicAdd(&s_sum[tx * 8 + c], csm[c]);
            atomicAdd(&s_sq[tx * 8 + c], csq[c]);
        }
        __syncthreads();
        if (tid < D) {
            atomicAdd(&g_colsum[tid], s_sum[tid]);
            atomicAdd(&g_colsumsq[tid], s_sq[tid]);
        }
    }
}

// ---------------- BN params from column stats ----------------
__global__ void meanvar_kernel(const float* __restrict__ g, const float* __restrict__ be) {
    int c = threadIdx.x;
    const float inv = 1.0f / (float)NN;
    float mu  = g_colsum[c] * inv;
    float var = g_colsumsq[c] * inv - mu * mu;
    var = fmaxf(var, 0.f);
    float sc = g[c] * rsqrtf(var + 1e-5f);
    g_scale[c] = sc;
    g_shift[c] = be[c] - mu * sc;
    g_colsum[c] = 0.f;
    g_colsumsq[c] = 0.f;
}

// ---------------- bn + (relu) + residual ----------------
__global__ void bn_res_kernel(float* __restrict__ out, int relu) {
    int i = blockIdx.x * blockDim.x + threadIdx.x;   // float4 index
    if (i >= NN * D / 4) return;
    int cb = (i * 4) & (D - 1);
    float4 t  = ((const float4*)g_tmp)[i];
    float4 hv = ((const float4*)g_h)[i];
    float4 sc = *(const float4*)(g_scale + cb);
    float4 sh = *(const float4*)(g_shift + cb);
    float4 v;
    v.x = t.x * sc.x + sh.x; v.y = t.y * sc.y + sh.y;
    v.z = t.z * sc.z + sh.z; v.w = t.w * sc.w + sh.w;
    if (relu) {
        v.x = fmaxf(v.x, 0.f); v.y = fmaxf(v.y, 0.f);
        v.z = fmaxf(v.z, 0.f); v.w = fmaxf(v.w, 0.f);
    }
    v.x += hv.x; v.y += hv.y; v.z += hv.z; v.w += hv.w;
    ((float4*)out)[i] = v;
}

// ---------------- launch ----------------
extern "C" void kernel_launch(void* const* d_in, const int* in_sizes, int n_in,
                              void* d_out, int out_size) {
    const float* x    = (const float*)d_in[0];
    const int*   ei   = (const int*)d_in[1];
    const float* ew   = (const float*)d_in[2];
    const float* W_in = (const float*)d_in[3];
    const float* b_in = (const float*)d_in[4];
    const float* P[18];
    for (int i = 0; i < 18; i++) P[i] = (const float*)d_in[5 + i];
    const int* row = ei;
    const int* col = ei + NE;
    float* out = (float*)d_out;

    float *ph, *pnbuf, *ptmp;
    cudaGetSymbolAddress((void**)&ph,    g_h);
    cudaGetSymbolAddress((void**)&pnbuf, g_nbuf);
    cudaGetSymbolAddress((void**)&ptmp,  g_tmp);

    const int SMEM_IN    = 128 * D * 4 + 128 * 16 * 4;   //  73728
    const int SMEM_LAYER = 256 * D * 4 + 128 * 16 * 4;   // 139264
    cudaFuncSetAttribute(gemm128<128, true,  false>,
                         cudaFuncAttributeMaxDynamicSharedMemorySize, SMEM_IN);
    cudaFuncSetAttribute(gemm128<256, false, true>,
                         cudaFuncAttributeMaxDynamicSharedMemorySize, SMEM_LAYER);

    const int GEMM_GRID = (NN + 127) / 128;   // 782

    zero_kernel<<<(NN + 255) / 256, 256>>>();
    hist_kernel<<<(NE + 255) / 256, 256>>>(col, ew);
    scan_kernel<<<1, 1024>>>();
    scatter_kernel<<<(NE + 255) / 256, 256>>>(row, col, ew);

    // h = relu(x @ W_in + b_in)
    gemm128<128, true, false><<<GEMM_GRID, 256, SMEM_IN>>>(
        x, W_in, nullptr, nullptr, b_in, nullptr, ph, NN);

    for (int l = 0; l < 3; l++) {
        aggregate_kernel<<<NN / 8, 256>>>();   // 12500 blocks, warp per node
        gemm128<256, false, true><<<GEMM_GRID, 256, SMEM_LAYER>>>(
            ph, P[6 * l + 0], pnbuf, P[6 * l + 2],
            P[6 * l + 1], P[6 * l + 3], ptmp, NN);
        meanvar_kernel<<<1, 128>>>(P[6 * l + 4], P[6 * l + 5]);
        bn_res_kernel<<<(NN * D / 4 + 255) / 256, 256>>>(
            (l < 2) ? ph : out, (l < 2) ? 1 : 0);
    }
}

// round 3
// speedup vs baseline: 1.4804x; 1.4804x over previous
#include <cuda_runtime.h>
#include <cuda_bf16.h>
#include <cstdint>

static constexpr int NN = 100000;
static constexpr int NE = 1600000;
static constexpr int D  = 128;

// ---------------- scratch (device globals; no allocations allowed) ----------
__device__ float g_h[NN * D];
__device__ float g_tmp[NN * D];
__device__ __nv_bfloat16 g_hhi[NN * D];
__device__ __nv_bfloat16 g_hlo[NN * D];
__device__ __nv_bfloat16 g_nbhi[NN * D];
__device__ __nv_bfloat16 g_nblo[NN * D];
__device__ __nv_bfloat16 g_wth[3 * D * 256];   // layer W^T [l][n][k]; k<128:Ws, k>=128:Wn
__device__ __nv_bfloat16 g_wtl[3 * D * 256];
__device__ __nv_bfloat16 g_wtih[D * D];        // input W^T [n][k]
__device__ __nv_bfloat16 g_wtil[D * D];
__device__ float g_biasc[3 * D];
__device__ int   g_counts[NN];
__device__ int   g_offsets[NN + 1];
__device__ int   g_cursor[NN];
__device__ float g_degw[NN];
__device__ int   g_csr_src[NE];
__device__ float g_csr_w[NE];
__device__ int   g_blocksum[512];
__device__ int   g_blockpref[512];
__device__ float g_colsum[D];
__device__ float g_colsumsq[D];
__device__ float g_scale[D];
__device__ float g_shift[D];

// ---------------- bf16 split ---------------------------------------------------
__device__ __forceinline__ void split_bf16(float v, __nv_bfloat16& hi, __nv_bfloat16& lo) {
    hi = __float2bfloat16(v);
    lo = __float2bfloat16(v - __bfloat162float(hi));
}
__device__ __forceinline__ void pack_split4(float v0, float v1, float v2, float v3,
                                            uint2& uh, uint2& ul) {
    __nv_bfloat16 h0, l0, h1, l1, h2, l2, h3, l3;
    split_bf16(v0, h0, l0); split_bf16(v1, h1, l1);
    split_bf16(v2, h2, l2); split_bf16(v3, h3, l3);
    __nv_bfloat162 a; a.x = h0; a.y = h1;
    __nv_bfloat162 b; b.x = h2; b.y = h3;
    __nv_bfloat162 c; c.x = l0; c.y = l1;
    __nv_bfloat162 d; d.x = l2; d.y = l3;
    uh = make_uint2(*(uint32_t*)&a, *(uint32_t*)&b);
    ul = make_uint2(*(uint32_t*)&c, *(uint32_t*)&d);
}

// ---------------- warp mma m16n8k16 bf16 ---------------------------------------
__device__ __forceinline__ void mma16816(float* c, uint32_t a0, uint32_t a1,
                                         uint32_t a2, uint32_t a3,
                                         uint32_t b0, uint32_t b1) {
    asm volatile(
        "mma.sync.aligned.m16n8k16.row.col.f32.bf16.bf16.f32 "
        "{%0,%1,%2,%3}, {%4,%5,%6,%7}, {%8,%9}, {%0,%1,%2,%3};"
        : "+f"(c[0]), "+f"(c[1]), "+f"(c[2]), "+f"(c[3])
        : "r"(a0), "r"(a1), "r"(a2), "r"(a3), "r"(b0), "r"(b1));
}

// ---------------- zero ----------------------------------------------------------
__global__ void zero_kernel() {
    int i = blockIdx.x * blockDim.x + threadIdx.x;
    if (i < NN) { g_counts[i] = 0; g_degw[i] = 0.f; }
    if (i < D)  { g_colsum[i] = 0.f; g_colsumsq[i] = 0.f; }
}

// ---------------- degree histogram ---------------------------------------------
__global__ void hist_kernel(const int* __restrict__ col, const float* __restrict__ ew) {
    int i = blockIdx.x * blockDim.x + threadIdx.x;
    if (i < NE) {
        int c = col[i];
        atomicAdd(&g_counts[c], 1);
        atomicAdd(&g_degw[c], ew[i]);
    }
}

// ---------------- 3-phase block scan -------------------------------------------
__global__ void scan1_kernel() {
    __shared__ int wsum[8];
    int tid = threadIdx.x, lane = tid & 31, wid = tid >> 5;
    int i = blockIdx.x * 256 + tid;
    int v = (i < NN) ? g_counts[i] : 0;
    int x = v;
    #pragma unroll
    for (int o = 1; o < 32; o <<= 1) {
        int t = __shfl_up_sync(0xffffffffu, x, o);
        if (lane >= o) x += t;
    }
    if (lane == 31) wsum[wid] = x;
    __syncthreads();
    if (tid < 8) {
        int s = wsum[tid];
        #pragma unroll
        for (int o = 1; o < 8; o <<= 1) {
            int t = __shfl_up_sync(0xffu, s, o, 8);
            if (tid >= o) s += t;
        }
        wsum[tid] = s;
    }
    __syncthreads();
    int excl = (wid ? wsum[wid - 1] : 0) + x - v;
    if (i < NN) g_offsets[i] = excl;
    if (tid == 255) g_blocksum[blockIdx.x] = wsum[7];
}

__global__ void scan2_kernel(int nb) {
    __shared__ int wsum[16];
    int tid = threadIdx.x, lane = tid & 31, wid = tid >> 5;
    int v = (tid < nb) ? g_blocksum[tid] : 0;
    int x = v;
    #pragma unroll
    for (int o = 1; o < 32; o <<= 1) {
        int t = __shfl_up_sync(0xffffffffu, x, o);
        if (lane >= o) x += t;
    }
    if (lane == 31) wsum[wid] = x;
    __syncthreads();
    if (tid < 16) {
        int s = wsum[tid];
        #pragma unroll
        for (int o = 1; o < 16; o <<= 1) {
            int t = __shfl_up_sync(0xffffu, s, o, 16);
            if (tid >= o) s += t;
        }
        wsum[tid] = s;
    }
    __syncthreads();
    int excl = (wid ? wsum[wid - 1] : 0) + x - v;
    if (tid < nb) g_blockpref[tid] = excl;
}

__global__ void scan3_kernel() {
    int i = blockIdx.x * blockDim.x + threadIdx.x;
    if (i < NN) {
        int off = g_offsets[i] + g_blockpref[i >> 8];
        g_offsets[i] = off;
        g_cursor[i] = off;
    }
    if (i == 0) g_offsets[NN] = NE;
}

// ---------------- CSR scatter ---------------------------------------------------
__global__ void scatter_kernel(const int* __restrict__ row, const int* __restrict__ col,
                               const float* __restrict__ ew) {
    int i = blockIdx.x * blockDim.x + threadIdx.x;
    if (i < NE) {
        int c = col[i];
        int p = atomicAdd(&g_cursor[c], 1);
        g_csr_src[p] = row[i];
        g_csr_w[p]   = ew[i];
    }
}

// ---------------- weight convert + transpose (once per launch) ------------------
__global__ void wconv_kernel(const float* __restrict__ Win,
                             const float* __restrict__ Ws0, const float* __restrict__ Wn0,
                             const float* __restrict__ Ws1, const float* __restrict__ Wn1,
                             const float* __restrict__ Ws2, const float* __restrict__ Wn2) {
    int i = blockIdx.x * blockDim.x + threadIdx.x;
    if (i < D * D) {
        int n = i >> 7, k = i & 127;
        float v = Win[k * D + n];
        __nv_bfloat16 h, l; split_bf16(v, h, l);
        g_wtih[i] = h; g_wtil[i] = l;
        return;
    }
    int j = i - D * D;
    if (j < 3 * D * 256) {
        int l = j / (D * 256), r = j % (D * 256);
        int n = r >> 8, k = r & 255;
        const float* Ws = (l == 0) ? Ws0 : (l == 1) ? Ws1 : Ws2;
        const float* Wn = (l == 0) ? Wn0 : (l == 1) ? Wn1 : Wn2;
        float v = (k < 128) ? Ws[k * D + n] : Wn[(k - 128) * D + n];
        __nv_bfloat16 h, lo; split_bf16(v, h, lo);
        g_wth[j] = h; g_wtl[j] = lo;
    }
}

__global__ void bias_kernel(const float* __restrict__ bs0, const float* __restrict__ bn0,
                            const float* __restrict__ bs1, const float* __restrict__ bn1,
                            const float* __restrict__ bs2, const float* __restrict__ bn2) {
    int tid = threadIdx.x;
    int l = tid >> 7, c = tid & 127;
    const float* bs = (l == 0) ? bs0 : (l == 1) ? bs1 : bs2;
    const float* bn = (l == 0) ? bn0 : (l == 1) ? bn1 : bn2;
    g_biasc[tid] = bs[c] + bn[c];
}

// ---------------- x -> bf16 hi/lo -----------------------------------------------
__global__ void xconv_kernel(const float* __restrict__ x) {
    int i = blockIdx.x * blockDim.x + threadIdx.x;
    if (i < NN * D) {
        __nv_bfloat16 h, l; split_bf16(x[i], h, l);
        g_nbhi[i] = h; g_nblo[i] = l;
    }
}

// ---------------- tensor-core GEMM via mma.sync (bf16 hi/lo 3-product) ----------
// Tile 128x128, 512 threads (16 warps, 4x4), K stepped by 16.
// B (both planes) staged fully in padded smem; A per-step with reg prefetch.
template <int KTOT, bool RELU, bool WRITE_BF16>
__global__ void __launch_bounds__(512, 1)
gemm_mma(const __nv_bfloat16* __restrict__ A1h, const __nv_bfloat16* __restrict__ A1l,
         const __nv_bfloat16* __restrict__ A2h, const __nv_bfloat16* __restrict__ A2l,
         const __nv_bfloat16* __restrict__ Bth, const __nv_bfloat16* __restrict__ Btl,
         const float* __restrict__ bias,
         float* __restrict__ outF, __nv_bfloat16* __restrict__ outH,
         __nv_bfloat16* __restrict__ outL, int M) {
    constexpr int BPAD = KTOT + 8;
    constexpr int NS = KTOT / 16;
    extern __shared__ char smem[];
    __nv_bfloat16* Bs = (__nv_bfloat16*)smem;          // [2][128][BPAD]
    __nv_bfloat16* As = Bs + 2 * 128 * BPAD;           // [2][128][24]
    float* s_bias = (float*)(As + 2 * 128 * 24);

    const int tid = threadIdx.x;
    const int lane = tid & 31, wid = tid >> 5;
    const int wm = wid >> 2, wn = wid & 3;
    const int qr = lane >> 2, qc = (lane & 3) * 2;
    const int row0 = blockIdx.x * 128;

    if (tid < D) s_bias[tid] = bias[tid];

    // stage B (hi+lo) into padded smem
    constexpr int BROW_U4 = KTOT / 8;
    for (int i = tid; i < 2 * 128 * BROW_U4; i += 512) {
        int plane = i / (128 * BROW_U4);
        int rem = i - plane * (128 * BROW_U4);
        int r = rem / BROW_U4;
        int j = rem - r * BROW_U4;
        const __nv_bfloat16* src = (plane ? Btl : Bth) + r * KTOT + j * 8;
        *(uint4*)(Bs + plane * 128 * BPAD + r * BPAD + j * 8) = *(const uint4*)src;
    }

    // A staging assignment: thread -> (plane, row, half)
    const int a_plane = tid >> 8;
    const int a_r     = (tid & 255) >> 1;
    const int a_half  = tid & 1;
    const int a_g     = row0 + a_r;

    uint4 pv;
    auto ld_step = [&](int s) {
        const __nv_bfloat16* src;
        int kb;
        if (KTOT == 256 && s >= 8) {
            src = a_plane ? A2l : A2h;
            kb = (s - 8) * 16 + a_half * 8;
        } else {
            src = a_plane ? A1l : A1h;
            kb = s * 16 + a_half * 8;
        }
        pv = make_uint4(0, 0, 0, 0);
        if (a_g < M) pv = *(const uint4*)(src + (size_t)a_g * D + kb);
    };
    auto st_step = [&]() {
        *(uint4*)(As + a_plane * 128 * 24 + a_r * 24 + a_half * 8) = pv;
    };

    float acc[2][4][4];
    #pragma unroll
    for (int mi = 0; mi < 2; mi++)
        #pragma unroll
        for (int ni = 0; ni < 4; ni++)
            #pragma unroll
            for (int r = 0; r < 4; r++) acc[mi][ni][r] = 0.f;

    ld_step(0);
    st_step();
    __syncthreads();

    for (int s = 0; s < NS; s++) {
        if (s + 1 < NS) ld_step(s + 1);

        const int kk = s * 16;
        uint32_t bh[4][2], bl[4][2];
        #pragma unroll
        for (int ni = 0; ni < 4; ni++) {
            const __nv_bfloat16* pH = Bs + (wn * 32 + ni * 8 + qr) * BPAD + kk + qc;
            const __nv_bfloat16* pL = pH + 128 * BPAD;
            bh[ni][0] = *(const uint32_t*)pH;
            bh[ni][1] = *(const uint32_t*)(pH + 8);
            bl[ni][0] = *(const uint32_t*)pL;
            bl[ni][1] = *(const uint32_t*)(pL + 8);
        }
        #pragma unroll
        for (int mi = 0; mi < 2; mi++) {
            const __nv_bfloat16* pH = As + (wm * 32 + mi * 16 + qr) * 24 + qc;
            const __nv_bfloat16* pL = pH + 128 * 24;
            uint32_t ah0 = *(const uint32_t*)pH;
            uint32_t ah1 = *(const uint32_t*)(pH + 8 * 24);
            uint32_t ah2 = *(const uint32_t*)(pH + 8);
            uint32_t ah3 = *(const uint32_t*)(pH + 8 * 24 + 8);
            uint32_t al0 = *(const uint32_t*)pL;
            uint32_t al1 = *(const uint32_t*)(pL + 8 * 24);
            uint32_t al2 = *(const uint32_t*)(pL + 8);
            uint32_t al3 = *(const uint32_t*)(pL + 8 * 24 + 8);
            #pragma unroll
            for (int ni = 0; ni < 4; ni++) {
                mma16816(acc[mi][ni], ah0, ah1, ah2, ah3, bh[ni][0], bh[ni][1]);
                mma16816(acc[mi][ni], ah0, ah1, ah2, ah3, bl[ni][0], bl[ni][1]);
                mma16816(acc[mi][ni], al0, al1, al2, al3, bh[ni][0], bh[ni][1]);
            }
        }
        if (s + 1 < NS) {
            __syncthreads();
            st_step();
            __syncthreads();
        }
    }

    // epilogue: bias (+relu) (+bf16 split write)
    #pragma unroll
    for (int mi = 0; mi < 2; mi++) {
        int r0 = row0 + wm * 32 + mi * 16 + qr;
        #pragma unroll
        for (int ni = 0; ni < 4; ni++) {
            int col = wn * 32 + ni * 8 + qc;
            float b0v = s_bias[col], b1v = s_bias[col + 1];
            float v00 = acc[mi][ni][0] + b0v, v01 = acc[mi][ni][1] + b1v;
            float v10 = acc[mi][ni][2] + b0v, v11 = acc[mi][ni][3] + b1v;
            if (RELU) {
                v00 = fmaxf(v00, 0.f); v01 = fmaxf(v01, 0.f);
                v10 = fmaxf(v10, 0.f); v11 = fmaxf(v11, 0.f);
            }
            if (r0 < M) {
                *(float2*)(outF + (size_t)r0 * D + col) = make_float2(v00, v01);
                if (WRITE_BF16) {
                    __nv_bfloat16 h0, l0, h1, l1;
                    split_bf16(v00, h0, l0); split_bf16(v01, h1, l1);
                    __nv_bfloat162 hh; hh.x = h0; hh.y = h1;
                    __nv_bfloat162 ll; ll.x = l0; ll.y = l1;
                    *(uint32_t*)(outH + (size_t)r0 * D + col) = *(uint32_t*)&hh;
                    *(uint32_t*)(outL + (size_t)r0 * D + col) = *(uint32_t*)&ll;
                }
            }
            if (r0 + 8 < M) {
                *(float2*)(outF + (size_t)(r0 + 8) * D + col) = make_float2(v10, v11);
                if (WRITE_BF16) {
                    __nv_bfloat16 h0, l0, h1, l1;
                    split_bf16(v10, h0, l0); split_bf16(v11, h1, l1);
                    __nv_bfloat162 hh; hh.x = h0; hh.y = h1;
                    __nv_bfloat162 ll; ll.x = l0; ll.y = l1;
                    *(uint32_t*)(outH + (size_t)(r0 + 8) * D + col) = *(uint32_t*)&hh;
                    *(uint32_t*)(outL + (size_t)(r0 + 8) * D + col) = *(uint32_t*)&ll;
                }
            }
        }
    }
}

// ---------------- per-node weighted-mean aggregation (warp per node) ------------
__global__ void aggregate_kernel() {
    int warp = (blockIdx.x * blockDim.x + threadIdx.x) >> 5;
    int lane = threadIdx.x & 31;
    if (warp >= NN) return;
    int start = g_offsets[warp], end = g_offsets[warp + 1];
    float4 acc = make_float4(0.f, 0.f, 0.f, 0.f);
    for (int e = start; e < end; e += 32) {
        int idx = e + lane;
        int s = 0; float w = 0.f;
        if (idx < end) { s = g_csr_src[idx]; w = g_csr_w[idx]; }
        int cnt = min(32, end - e);
        for (int j = 0; j < cnt; j++) {
            int   sj = __shfl_sync(0xffffffffu, s, j);
            float wj = __shfl_sync(0xffffffffu, w, j);
            float4 v = *(const float4*)(g_h + (size_t)sj * D + lane * 4);
            acc.x += v.x * wj; acc.y += v.y * wj;
            acc.z += v.z * wj; acc.w += v.w * wj;
        }
    }
    float dg = fmaxf(g_degw[warp], 1.0f);
    float inv = 1.0f / dg;
    acc.x *= inv; acc.y *= inv; acc.z *= inv; acc.w *= inv;
    uint2 uh, ul;
    pack_split4(acc.x, acc.y, acc.z, acc.w, uh, ul);
    *(uint2*)(g_nbhi + (size_t)warp * D + lane * 4) = uh;
    *(uint2*)(g_nblo + (size_t)warp * D + lane * 4) = ul;
}

// ---------------- column sum/sumsq reduction over g_tmp -------------------------
__global__ void colreduce_kernel() {
    __shared__ float ss[256], sq[256];
    int tid = threadIdx.x;
    int col = tid & 127, half = tid >> 7;
    int rbase = blockIdx.x * 256;
    int rend = min(rbase + 256, NN);
    float s = 0.f, q = 0.f;
    for (int r = rbase + half; r < rend; r += 2) {
        float v = g_tmp[(size_t)r * D + col];
        s += v; q += v * v;
    }
    ss[tid] = s; sq[tid] = q;
    __syncthreads();
    if (tid < 128) {
        atomicAdd(&g_colsum[col],   ss[tid] + ss[tid + 128]);
        atomicAdd(&g_colsumsq[col], sq[tid] + sq[tid + 128]);
    }
}

// ---------------- BN params from column stats -----------------------------------
__global__ void meanvar_kernel(const float* __restrict__ g, const float* __restrict__ be) {
    int c = threadIdx.x;
    const float inv = 1.0f / (float)NN;
    float mu  = g_colsum[c] * inv;
    float var = g_colsumsq[c] * inv - mu * mu;
    var = fmaxf(var, 0.f);
    float sc = g[c] * rsqrtf(var + 1e-5f);
    g_scale[c] = sc;
    g_shift[c] = be[c] - mu * sc;
    g_colsum[c] = 0.f;
    g_colsumsq[c] = 0.f;
}

// ---------------- bn + (relu) + residual (+ bf16 hi/lo for next layer) ----------
__global__ void bn_res_kernel(float* __restrict__ out, __nv_bfloat16* __restrict__ oh,
                              __nv_bfloat16* __restrict__ ol, int relu) {
    int i = blockIdx.x * blockDim.x + threadIdx.x;   // float4 index
    if (i >= NN * D / 4) return;
    int cb = (i * 4) & (D - 1);
    float4 t  = ((const float4*)g_tmp)[i];
    float4 hv = ((const float4*)g_h)[i];
    float4 sc = *(const float4*)(g_scale + cb);
    float4 sh = *(const float4*)(g_shift + cb);
    float4 v;
    v.x = t.x * sc.x + sh.x; v.y = t.y * sc.y + sh.y;
    v.z = t.z * sc.z + sh.z; v.w = t.w * sc.w + sh.w;
    if (relu) {
        v.x = fmaxf(v.x, 0.f); v.y = fmaxf(v.y, 0.f);
        v.z = fmaxf(v.z, 0.f); v.w = fmaxf(v.w, 0.f);
    }
    v.x += hv.x; v.y += hv.y; v.z += hv.z; v.w += hv.w;
    ((float4*)out)[i] = v;
    if (oh) {
        uint2 uh, ul;
        pack_split4(v.x, v.y, v.z, v.w, uh, ul);
        *(uint2*)(oh + (size_t)i * 4) = uh;
        *(uint2*)(ol + (size_t)i * 4) = ul;
    }
}

// ---------------- launch ---------------------------------------------------------
extern "C" void kernel_launch(void* const* d_in, const int* in_sizes, int n_in,
                              void* d_out, int out_size) {
    const float* x    = (const float*)d_in[0];
    const int*   ei   = (const int*)d_in[1];
    const float* ew   = (const float*)d_in[2];
    const float* W_in = (const float*)d_in[3];
    const float* b_in = (const float*)d_in[4];
    const float* P[18];
    for (int i = 0; i < 18; i++) P[i] = (const float*)d_in[5 + i];
    const int* row = ei;
    const int* col = ei + NE;
    float* out = (float*)d_out;

    float *ph, *ptmp, *pbiasc;
    __nv_bfloat16 *phhi, *phlo, *pnbhi, *pnblo, *pwth, *pwtl, *pwtih, *pwtil;
    cudaGetSymbolAddress((void**)&ph,    g_h);
    cudaGetSymbolAddress((void**)&ptmp,  g_tmp);
    cudaGetSymbolAddress((void**)&phhi,  g_hhi);
    cudaGetSymbolAddress((void**)&phlo,  g_hlo);
    cudaGetSymbolAddress((void**)&pnbhi, g_nbhi);
    cudaGetSymbolAddress((void**)&pnblo, g_nblo);
    cudaGetSymbolAddress((void**)&pwth,  g_wth);
    cudaGetSymbolAddress((void**)&pwtl,  g_wtl);
    cudaGetSymbolAddress((void**)&pwtih, g_wtih);
    cudaGetSymbolAddress((void**)&pwtil, g_wtil);
    cudaGetSymbolAddress((void**)&pbiasc, g_biasc);

    // smem: B[2][128][BPAD] + A[2][128][24] + bias
    const int SM128 = (2 * 128 * 136 + 2 * 128 * 24) * 2 + 512;   //  82432
    const int SM256 = (2 * 128 * 264 + 2 * 128 * 24) * 2 + 512;   // 147968
    cudaFuncSetAttribute(gemm_mma<128, true,  true>,
                         cudaFuncAttributeMaxDynamicSharedMemorySize, SM128);
    cudaFuncSetAttribute(gemm_mma<256, false, false>,
                         cudaFuncAttributeMaxDynamicSharedMemorySize, SM256);

    const int GEMM_GRID = (NN + 127) / 128;   // 782
    const int SCAN_NB   = (NN + 255) / 256;   // 391

    zero_kernel<<<(NN + 255) / 256, 256>>>();
    hist_kernel<<<(NE + 255) / 256, 256>>>(col, ew);
    scan1_kernel<<<SCAN_NB, 256>>>();
    scan2_kernel<<<1, 512>>>(SCAN_NB);
    scan3_kernel<<<SCAN_NB, 256>>>();
    scatter_kernel<<<(NE + 255) / 256, 256>>>(row, col, ew);

    wconv_kernel<<<(D * D + 3 * D * 256 + 255) / 256, 256>>>(
        W_in, P[0], P[2], P[6], P[8], P[12], P[14]);
    bias_kernel<<<1, 384>>>(P[1], P[3], P[7], P[9], P[13], P[15]);
    xconv_kernel<<<(NN * D + 255) / 256, 256>>>(x);

    // h = relu(x @ W_in + b_in)   (x hi/lo staged in nb buffers)
    gemm_mma<128, true, true><<<GEMM_GRID, 512, SM128>>>(
        pnbhi, pnblo, nullptr, nullptr, pwtih, pwtil, b_in, ph, phhi, phlo, NN);

    for (int l = 0; l < 3; l++) {
        aggregate_kernel<<<NN / 8, 256>>>();
        gemm_mma<256, false, false><<<GEMM_GRID, 512, SM256>>>(
            phhi, phlo, pnbhi, pnblo,
            pwth + l * D * 256, pwtl + l * D * 256, pbiasc + l * D,
            ptmp, nullptr, nullptr, NN);
        colreduce_kernel<<<SCAN_NB, 256>>>();
        meanvar_kernel<<<1, 128>>>(P[6 * l + 4], P[6 * l + 5]);
        bn_res_kernel<<<(NN * D / 4 + 255) / 256, 256>>>(
            (l < 2) ? ph : out,
            (l < 2) ? phhi : nullptr,
            (l < 2) ? phlo : nullptr,
            (l < 2) ? 1 : 0);
    }
}